// round 16
// baseline (speedup 1.0000x reference)
#include <cuda_runtime.h>
#include <math_constants.h>

#define BDIM 1024

// qr layout: per-warp blocks of 32 lanes, lane stride 22 ull (44 words = 12 mod 32
// -> 8-lane LDS.128 phases perfectly tile all 32 banks), ap-major: [ap*4 + p].
#define QR_LANE_ULL   22
#define QR_WARP_ULL   (32*QR_LANE_ULL)            // 704
#define QR2_ULLS      (32*QR_WARP_ULL)            // 22528
#define QR2_FLOATS    (QR2_ULLS*2)                // 45056
#define VSTRIDE    72                             // 8 mod 32 -> row de-banking
#define VSZ        (66*VSTRIDE)                   // 4752 ; data (r,c) -> (r+1, vcol(c+1))
#define WST_FLOATS 270                            // staged qw0[90], qb[10], qw1[90], fc[80]
#define WK_FLOATS  172
#define XS_FLOATS  (2*68*68)                      // 9248, overlays qr2 (phases 0-1)
#define SMEM_FLOATS (QR2_FLOATS + 2*VSZ + WST_FLOATS + WK_FLOATS)
#define SMEM_BYTES (SMEM_FLOATS*4)                // 220,008 B

typedef unsigned long long ull;

__device__ float g_Kq[162];
__device__ float g_bq[9];
__device__ float g_wq2[90];       // action-pair packed v-channel weights (45 ull)

__constant__ float c_wq2[90];     // staged copy; warp-uniform LDCU in the hot loop

// column swizzle: padded col pc -> word col; +4 shift for pc>=32 breaks the
// +32-word same-bank collision. Boundary 32 is 4-aligned (no vector straddle).
__device__ __forceinline__ int vcol(int pc) { return pc + ((pc >= 32) ? 4 : 0); }

// ---------------- setup: compose 2-stage conv weights + pack loop weights ---------
__global__ void vin_setup(const float* __restrict__ h_w,
                          const float* __restrict__ h_b,
                          const float* __restrict__ r_w,
                          const float* __restrict__ q_w)
{
    int t = threadIdx.x;
    if (t < 162) {
        int q = t / 18;
        int rest = t % 18;
        float acc = 0.f;
        #pragma unroll 10
        for (int m = 0; m < 150; m++)
            acc += r_w[m*9 + q] * h_w[m*18 + rest];
        g_Kq[t] = acc;
    } else if (t < 171) {
        int q = t - 162;
        float acc = 0.f;
        #pragma unroll 10
        for (int m = 0; m < 150; m++)
            acc += r_w[m*9 + q] * h_b[m];
        g_bq[q] = acc;
    }
    // action-pair packing of q_w's v-channel: pair (w_2a, w_2a+1) per offset
    if (t >= 192 && t < 192 + 90) {
        int i = t - 192;                  // i = a*9 + t9
        int a = i / 9, t9 = i % 9;
        g_wq2[(a >> 1)*18 + t9*2 + (a & 1)] = q_w[a*18 + 9 + t9];
    }
}

// ---------------- packed f32x2 helpers -------------------------------------------
__device__ __forceinline__ ull pk2(float lo, float hi){
    ull r;
    asm("mov.b64 %0, {%1, %2};" : "=l"(r) : "f"(lo), "f"(hi));
    return r;
}
__device__ __forceinline__ void upk2(ull v, float& lo, float& hi){
    asm("mov.b64 {%0, %1}, %2;" : "=f"(lo), "=f"(hi) : "l"(v));
}
__device__ __forceinline__ ull fma2(ull a, ull b, ull c){
    ull d;
    asm("fma.rn.f32x2 %0, %1, %2, %3;" : "=l"(d) : "l"(a), "l"(b), "l"(c));
    return d;
}

// ---------------- main: one CTA per image; 1024 thr, 4 px/thread ------------------
__global__ void __launch_bounds__(BDIM, 1)
vin_main(const float* __restrict__ xg,
         const int*   __restrict__ pos_x,
         const int*   __restrict__ pos_y,
         const float* __restrict__ r_b,
         const float* __restrict__ q_w,
         const float* __restrict__ q_b,
         const float* __restrict__ fc_w,
         float*       __restrict__ out)
{
    extern __shared__ float smem[];
    float* qr2f = smem;                       // per-lane qr blocks, ap-major
    float* vA   = smem + QR2_FLOATS;          // 66 x 72, zero ring pad, swizzled cols
    float* vB   = vA + VSZ;
    float* wst  = vB + VSZ;                   // [0:90) qw0, [90:100) qb, [100:190) qw1, [190:270) fc
    float* wK   = wst + WST_FLOATS;           // composed r-conv weights (171)
    float* xsS  = smem;                       // x tile 2x68x68, overlays qr2
    ull*   qr2  = (ull*)qr2f;
    const ull* cw = (const ull*)c_wq2;        // warp-uniform constant loads (LDCU)

    const int b   = blockIdx.x;
    const int tid = threadIdx.x;
    const int row = tid >> 4;                 // 0..63
    const int cg  = tid & 15;
    const int c0  = cg << 2;                  // 4 pixels per thread
    ull* const myqr = qr2 + (tid >> 5) * QR_WARP_ULL + (tid & 31) * QR_LANE_ULL;

    // ---- phase 0: zero pads, stage weights, load x --------------------------------
    for (int i = tid; i < XS_FLOATS; i += BDIM) xsS[i] = 0.f;
    for (int i = tid; i < 2*VSZ; i += BDIM) vA[i] = 0.f;
    if (tid < 171) wK[tid] = (tid < 162) ? g_Kq[tid] : g_bq[tid - 162];
    // stage q_w / q_b / fc_w into SMEM (threads 192..461)
    if (tid >= 192 && tid < 192 + 270) {
        int i = tid - 192;
        float v;
        if (i < 90)       { int a = i/9, t9 = i%9; v = q_w[a*18 + t9]; }        // qw0
        else if (i < 100) { v = q_b[i-90]; }                                     // qb
        else if (i < 190) { int j = i-100; int a = j/9, t9 = j%9; v = q_w[a*18 + 9 + t9]; } // qw1
        else              { v = fc_w[i-190]; }                                   // fc
        wst[i] = v;
    }
    __syncthreads();

    const float* xb = xg + (size_t)b * 8192;
    for (int i = tid; i < 8192; i += BDIM) {
        int c = i >> 12;
        int y = (i >> 6) & 63;
        int x = i & 63;
        xsS[c*4624 + (y+2)*68 + (x+2)] = xb[i];
    }
    __syncthreads();

    // ---- phase 1: r = composed conv of x, exact boundary masking ------------------
    {
        float racc[4];
        const float rb = r_b[0];
        #pragma unroll
        for (int p = 0; p < 4; p++) racc[p] = rb;
        #pragma unroll
        for (int q = 0; q < 9; q++) {
            const int qi = q / 3, qj = q % 3;
            const int yy = row + qi - 1;
            const bool rowok = (yy >= 0) && (yy < 64);
            float kw[18];
            #pragma unroll
            for (int t = 0; t < 18; t++) kw[t] = wK[q*18 + t];
            const float bqv = wK[162 + q];
            #pragma unroll
            for (int p = 0; p < 4; p++) {
                int xx = c0 + p + qj - 1;
                if (rowok && xx >= 0 && xx < 64) {
                    float t = bqv;
                    #pragma unroll
                    for (int c = 0; c < 2; c++)
                        #pragma unroll
                        for (int s = 0; s < 3; s++)
                            #pragma unroll
                            for (int u = 0; u < 3; u++)
                                t += kw[c*9 + s*3 + u] *
                                     xsS[c*4624 + (yy+s+1)*68 + (xx+u+1)];
                    racc[p] += t;
                }
            }
        }
        __syncthreads();   // all xsS reads done before qr2 overlay written (phase 2)
        #pragma unroll
        for (int p = 0; p < 4; p++)
            vA[(row+1)*VSTRIDE + vcol(c0 + p + 1)] = racc[p];
    }
    __syncthreads();

    // ---- phase 2: loop-invariant qr = conv(r, qw0) + qb, ap-major layout ----------
    {
        #pragma unroll
        for (int p = 0; p < 4; p++) {
            const int x = c0 + p;
            float win[9];
            #pragma unroll
            for (int s = 0; s < 3; s++)
                #pragma unroll
                for (int u = 0; u < 3; u++)
                    win[s*3+u] = vA[(row+s)*VSTRIDE + vcol(x + u)];
            float qt[10];
            #pragma unroll
            for (int a = 0; a < 10; a++) {
                float t = wst[90 + a];
                #pragma unroll
                for (int s = 0; s < 3; s++)
                    #pragma unroll
                    for (int u = 0; u < 3; u++)
                        t += wst[a*9 + s*3 + u] * win[s*3+u];
                qt[a] = t;
            }
            #pragma unroll
            for (int ap = 0; ap < 5; ap++)
                myqr[ap*4 + p] = pk2(qt[2*ap], qt[2*ap+1]);
        }
    }
    __syncthreads();
    // clear vA (held r): v0 = 0
    for (int i = tid; i < VSZ; i += BDIM) vA[i] = 0.f;
    __syncthreads();

    // ---- phase 3: K=50 VI steps; 4 px/thread, weights via uniform-constant port ---
    const int sc0 = vcol(c0);                 // window padded cols c0..c0+5
    const int sc4 = vcol(c0 + 4);
    int sw = 0;

    #pragma unroll 1
    for (int k = 0; k < 50; k++) {
        const float* vin  = vA + sw;
        float*       vout = vA + (sw ^ VSZ);
        sw ^= VSZ;

        // duplicated window: 3 rows x 6 cols, (v,v) pairs; conflict-free LDS.128/64
        ull dw[18];
        #pragma unroll
        for (int s = 0; s < 3; s++) {
            const float* wr = vin + (row + s)*VSTRIDE;
            float4 f0 = *(const float4*)(wr + sc0);
            float2 f1 = *(const float2*)(wr + sc4);
            dw[s*6 + 0] = pk2(f0.x, f0.x);
            dw[s*6 + 1] = pk2(f0.y, f0.y);
            dw[s*6 + 2] = pk2(f0.z, f0.z);
            dw[s*6 + 3] = pk2(f0.w, f0.w);
            dw[s*6 + 4] = pk2(f1.x, f1.x);
            dw[s*6 + 5] = pk2(f1.y, f1.y);
        }

        float vnew[4];
        #pragma unroll
        for (int ap = 0; ap < 5; ap++) {
            ull w[9];
            #pragma unroll
            for (int t = 0; t < 9; t++) w[t] = cw[ap*9 + t];    // LDCU (uniform port)
            // 4 accumulators: 2 conflict-free LDS.128 (ap-major, 16B-aligned)
            const ulonglong2* qp = (const ulonglong2*)(myqr + ap*4);
            ulonglong2 q01 = qp[0], q23 = qp[1];
            ull acc[4] = {q01.x, q01.y, q23.x, q23.y};
            #pragma unroll
            for (int p = 0; p < 4; p++) {
                ull a = acc[p];
                #pragma unroll
                for (int s = 0; s < 3; s++)
                    #pragma unroll
                    for (int u = 0; u < 3; u++)
                        a = fma2(dw[s*6 + p + u], w[s*3+u], a);
                float lo, hi; upk2(a, lo, hi);
                float m = fmaxf(lo, hi);
                vnew[p] = (ap == 0) ? m : fmaxf(vnew[p], m);
            }
        }
        #pragma unroll
        for (int p = 0; p < 4; p++)
            vout[(row+1)*VSTRIDE + vcol(c0 + 1 + p)] = vnew[p];
        __syncthreads();
    }
    // final v lives in vA (k=49 wrote vA)

    const int prow = pos_x[b];
    const int pcol = pos_y[b];
    if (row == prow && (pcol >> 2) == cg) {
        float win[9];
        #pragma unroll
        for (int s = 0; s < 3; s++)
            #pragma unroll
            for (int u = 0; u < 3; u++)
                win[s*3+u] = vA[(prow+s)*VSTRIDE + vcol(pcol + u)];
        float qv[10];
        #pragma unroll
        for (int ap = 0; ap < 5; ap++) {
            float lo, hi; upk2(myqr[ap*4 + (pcol & 3)], lo, hi);
            qv[2*ap] = lo; qv[2*ap+1] = hi;
        }
        #pragma unroll
        for (int a = 0; a < 10; a++) {
            float t = qv[a];
            #pragma unroll
            for (int s = 0; s < 3; s++)
                #pragma unroll
                for (int u = 0; u < 3; u++)
                    t += wst[100 + a*9 + s*3 + u] * win[s*3+u];
            qv[a] = t;
        }
        #pragma unroll
        for (int j = 0; j < 8; j++) {
            float o = 0.f;
            #pragma unroll
            for (int a = 0; a < 10; a++) o += qv[a] * wst[190 + j*10 + a];
            out[b*8 + j] = o;
        }
    }
}

// ---------------- launch: setup -> stage constants -> main ------------------------
extern "C" void kernel_launch(void* const* d_in, const int* in_sizes, int n_in,
                              void* d_out, int out_size)
{
    const float* x     = (const float*)d_in[0];
    const int*   pos_x = (const int*)  d_in[1];
    const int*   pos_y = (const int*)  d_in[2];
    const float* h_w   = (const float*)d_in[3];
    const float* h_b   = (const float*)d_in[4];
    const float* r_w   = (const float*)d_in[5];
    const float* r_b   = (const float*)d_in[6];
    const float* q_w   = (const float*)d_in[7];
    const float* q_b   = (const float*)d_in[8];
    const float* fc_w  = (const float*)d_in[9];

    (void)in_sizes; (void)n_in; (void)out_size;

    cudaFuncSetAttribute(vin_main, cudaFuncAttributeMaxDynamicSharedMemorySize,
                         SMEM_BYTES);

    vin_setup<<<1, 288>>>(h_w, h_b, r_w, q_w);

    void* wq2_src = nullptr;
    cudaGetSymbolAddress(&wq2_src, g_wq2);
    cudaMemcpyToSymbolAsync(c_wq2, wq2_src, 90*sizeof(float), 0,
                            cudaMemcpyDeviceToDevice, 0);

    vin_main<<<128, BDIM, SMEM_BYTES>>>(x, pos_x, pos_y, r_b, q_w, q_b, fc_w,
                                        (float*)d_out);
}

// round 17
// speedup vs baseline: 1.2327x; 1.2327x over previous
#include <cuda_runtime.h>
#include <math_constants.h>

#define BDIM 512

// qr layout: per-warp blocks of 32 lanes, lane stride 42 ull (84 words = 20 mod 32
// -> conflict-free LDS.128 phases), ap-major within lane: index [ap*8 + p].
#define QR_LANE_ULL   42
#define QR_WARP_ULL   (32*QR_LANE_ULL)            // 1344
#define QR2_ULLS      (16*QR_WARP_ULL)            // 21504
#define QR2_FLOATS    (QR2_ULLS*2)                // 43008
#define VSTRIDE    72                             // 8 mod 32 -> row de-banking
#define VSZ        (66*VSTRIDE)                   // 4752 ; data (r,c) -> (r+1, vcol(c+1))
#define WST_FLOATS 270                            // staged qw0[90], qb[10], qw1[90], fc[80]
#define WK_FLOATS  172
#define XS_FLOATS  (2*68*68)                      // 9248, overlays qr2 (phases 0-1)
#define SMEM_FLOATS (QR2_FLOATS + 2*VSZ + WST_FLOATS + WK_FLOATS)
#define SMEM_BYTES (SMEM_FLOATS*4)

typedef unsigned long long ull;

__device__ float g_Kq[162];
__device__ float g_bq[9];
__device__ float g_wq2[90];       // action-pair packed v-channel weights (45 ull)

__constant__ float c_wq2[90];     // staged copy; warp-uniform LDCU in the hot loop

// column swizzle: padded col pc -> word col; +4 shift for pc>=32 breaks the
// +32-word same-bank collision. Boundary 32 is 4-aligned (no vector straddle).
__device__ __forceinline__ int vcol(int pc) { return pc + ((pc >= 32) ? 4 : 0); }

// ---------------- setup: compose 2-stage conv weights + pack loop weights ---------
__global__ void vin_setup(const float* __restrict__ h_w,
                          const float* __restrict__ h_b,
                          const float* __restrict__ r_w,
                          const float* __restrict__ q_w)
{
    int t = threadIdx.x;
    if (t < 162) {
        int q = t / 18;
        int rest = t % 18;
        float acc = 0.f;
        #pragma unroll 10
        for (int m = 0; m < 150; m++)
            acc += r_w[m*9 + q] * h_w[m*18 + rest];
        g_Kq[t] = acc;
    } else if (t < 171) {
        int q = t - 162;
        float acc = 0.f;
        #pragma unroll 10
        for (int m = 0; m < 150; m++)
            acc += r_w[m*9 + q] * h_b[m];
        g_bq[q] = acc;
    }
    // action-pair packing of q_w's v-channel: pair (w_2a, w_2a+1) per offset
    if (t >= 192 && t < 192 + 90) {
        int i = t - 192;                  // i = a*9 + t9
        int a = i / 9, t9 = i % 9;
        g_wq2[(a >> 1)*18 + t9*2 + (a & 1)] = q_w[a*18 + 9 + t9];
    }
}

// ---------------- packed f32x2 helpers -------------------------------------------
__device__ __forceinline__ ull pk2(float lo, float hi){
    ull r;
    asm("mov.b64 %0, {%1, %2};" : "=l"(r) : "f"(lo), "f"(hi));
    return r;
}
__device__ __forceinline__ void upk2(ull v, float& lo, float& hi){
    asm("mov.b64 {%0, %1}, %2;" : "=f"(lo), "=f"(hi) : "l"(v));
}
__device__ __forceinline__ ull fma2(ull a, ull b, ull c){
    ull d;
    asm("fma.rn.f32x2 %0, %1, %2, %3;" : "=l"(d) : "l"(a), "l"(b), "l"(c));
    return d;
}

// ---------------- main: one CTA per image; 512 thr, 2 rows x 4 cols / thread ------
__global__ void __launch_bounds__(BDIM, 1)
vin_main(const float* __restrict__ xg,
         const int*   __restrict__ pos_x,
         const int*   __restrict__ pos_y,
         const float* __restrict__ r_b,
         const float* __restrict__ q_w,
         const float* __restrict__ q_b,
         const float* __restrict__ fc_w,
         float*       __restrict__ out)
{
    extern __shared__ float smem[];
    float* qr2f = smem;                       // per-lane qr blocks, ap-major
    float* vA   = smem + QR2_FLOATS;          // 66 x 72, zero ring pad, swizzled cols
    float* vB   = vA + VSZ;
    float* wst  = vB + VSZ;                   // [0:90) qw0, [90:100) qb, [100:190) qw1, [190:270) fc
    float* wK   = wst + WST_FLOATS;           // composed r-conv weights (171)
    float* xsS  = smem;                       // x tile 2x68x68, overlays qr2
    ull*   qr2  = (ull*)qr2f;
    const ull* cw = (const ull*)c_wq2;        // warp-uniform constant loads (LDCU)

    const int b   = blockIdx.x;
    const int tid = threadIdx.x;
    const int rp  = tid >> 4;                 // row-pair 0..31 -> rows 2rp, 2rp+1
    const int cg  = tid & 15;
    const int c0  = cg << 2;                  // 4 cols per thread
    const int r0  = rp << 1;                  // top row of the pair
    ull* const myqr = qr2 + (tid >> 5) * QR_WARP_ULL + (tid & 31) * QR_LANE_ULL;

    // ---- phase 0: zero pads, stage weights, load x --------------------------------
    for (int i = tid; i < XS_FLOATS; i += BDIM) xsS[i] = 0.f;
    for (int i = tid; i < 2*VSZ; i += BDIM) vA[i] = 0.f;
    if (tid < 171) wK[tid] = (tid < 162) ? g_Kq[tid] : g_bq[tid - 162];
    // stage q_w / q_b / fc_w into SMEM (threads 192..461)
    if (tid >= 192 && tid < 192 + 270) {
        int i = tid - 192;
        float v;
        if (i < 90)       { int a = i/9, t9 = i%9; v = q_w[a*18 + t9]; }        // qw0
        else if (i < 100) { v = q_b[i-90]; }                                     // qb
        else if (i < 190) { int j = i-100; int a = j/9, t9 = j%9; v = q_w[a*18 + 9 + t9]; } // qw1
        else              { v = fc_w[i-190]; }                                   // fc
        wst[i] = v;
    }
    __syncthreads();

    const float* xb = xg + (size_t)b * 8192;
    for (int i = tid; i < 8192; i += BDIM) {
        int c = i >> 12;
        int y = (i >> 6) & 63;
        int x = i & 63;
        xsS[c*4624 + (y+2)*68 + (x+2)] = xb[i];
    }
    __syncthreads();

    // ---- phase 1: r = composed conv of x, exact boundary masking ------------------
    // pixel p: R = r0 + (p>>2), C = c0 + (p&3)
    {
        float racc[8];
        const float rb = r_b[0];
        #pragma unroll
        for (int p = 0; p < 8; p++) racc[p] = rb;
        #pragma unroll
        for (int q = 0; q < 9; q++) {
            const int qi = q / 3, qj = q % 3;
            float kw[18];
            #pragma unroll
            for (int t = 0; t < 18; t++) kw[t] = wK[q*18 + t];
            const float bqv = wK[162 + q];
            #pragma unroll
            for (int p = 0; p < 8; p++) {
                const int R  = r0 + (p >> 2);
                const int C  = c0 + (p & 3);
                const int yy = R + qi - 1;
                const int xx = C + qj - 1;
                if (yy >= 0 && yy < 64 && xx >= 0 && xx < 64) {
                    float t = bqv;
                    #pragma unroll
                    for (int c = 0; c < 2; c++)
                        #pragma unroll
                        for (int s = 0; s < 3; s++)
                            #pragma unroll
                            for (int u = 0; u < 3; u++)
                                t += kw[c*9 + s*3 + u] *
                                     xsS[c*4624 + (yy+s+1)*68 + (xx+u+1)];
                    racc[p] += t;
                }
            }
        }
        __syncthreads();   // all xsS reads done before qr2 overlay written (phase 2)
        #pragma unroll
        for (int p = 0; p < 8; p++)
            vA[(r0 + (p>>2) + 1)*VSTRIDE + vcol(c0 + (p&3) + 1)] = racc[p];
    }
    __syncthreads();

    // ---- phase 2: loop-invariant qr = conv(r, qw0) + qb, ap-major layout ----------
    {
        #pragma unroll
        for (int p = 0; p < 8; p++) {
            const int R = r0 + (p >> 2);
            const int C = c0 + (p & 3);
            float win[9];
            #pragma unroll
            for (int s = 0; s < 3; s++)
                #pragma unroll
                for (int u = 0; u < 3; u++)
                    win[s*3+u] = vA[(R+s)*VSTRIDE + vcol(C + u)];
            float qt[10];
            #pragma unroll
            for (int a = 0; a < 10; a++) {
                float t = wst[90 + a];
                #pragma unroll
                for (int s = 0; s < 3; s++)
                    #pragma unroll
                    for (int u = 0; u < 3; u++)
                        t += wst[a*9 + s*3 + u] * win[s*3+u];
                qt[a] = t;
            }
            #pragma unroll
            for (int ap = 0; ap < 5; ap++)
                myqr[ap*8 + p] = pk2(qt[2*ap], qt[2*ap+1]);
        }
    }
    __syncthreads();
    // clear vA (held r): v0 = 0
    for (int i = tid; i < VSZ; i += BDIM) vA[i] = 0.f;
    __syncthreads();

    // ---- phase 3: K=50 VI steps; 2x4 window (4 rows x 6 cols), LDCU weights -------
    const int sc0 = vcol(c0);                 // padded cols c0..c0+5 (actual c0-1..c0+4)
    const int sc4 = vcol(c0 + 4);
    int sw = 0;

    #pragma unroll 1
    for (int k = 0; k < 50; k++) {
        const float* vin  = vA + sw;
        float*       vout = vA + (sw ^ VSZ);
        sw ^= VSZ;

        // duplicated window: 4 rows x 6 cols, (v,v) pairs; LDS.128 + LDS.64 per row
        ull dw[24];
        #pragma unroll
        for (int s = 0; s < 4; s++) {
            const float* wr = vin + (r0 + s)*VSTRIDE;   // padded rows r0..r0+3
            float4 f0 = *(const float4*)(wr + sc0);
            float2 f1 = *(const float2*)(wr + sc4);
            dw[s*6 + 0] = pk2(f0.x, f0.x);
            dw[s*6 + 1] = pk2(f0.y, f0.y);
            dw[s*6 + 2] = pk2(f0.z, f0.z);
            dw[s*6 + 3] = pk2(f0.w, f0.w);
            dw[s*6 + 4] = pk2(f1.x, f1.x);
            dw[s*6 + 5] = pk2(f1.y, f1.y);
        }

        float vnew[8];
        #pragma unroll
        for (int ap = 0; ap < 5; ap++) {
            ull w[9];
            #pragma unroll
            for (int t = 0; t < 9; t++) w[t] = cw[ap*9 + t];    // LDCU (uniform port)
            // 8 accumulators: 4 conflict-free LDS.128 (ap-major, 16B-aligned)
            const ulonglong2* qp = (const ulonglong2*)(myqr + ap*8);
            ulonglong2 q01 = qp[0], q23 = qp[1], q45 = qp[2], q67 = qp[3];
            ull acc[8] = {q01.x, q01.y, q23.x, q23.y, q45.x, q45.y, q67.x, q67.y};
            #pragma unroll
            for (int p = 0; p < 8; p++) {
                const int pr = p >> 2;        // row within pair
                const int pc = p & 3;         // col within group
                ull a = acc[p];
                #pragma unroll
                for (int s = 0; s < 3; s++)
                    #pragma unroll
                    for (int u = 0; u < 3; u++)
                        a = fma2(dw[(pr+s)*6 + pc + u], w[s*3+u], a);
                float lo, hi; upk2(a, lo, hi);
                float m = fmaxf(lo, hi);
                vnew[p] = (ap == 0) ? m : fmaxf(vnew[p], m);
            }
        }
        #pragma unroll
        for (int p = 0; p < 8; p++)
            vout[(r0 + (p>>2) + 1)*VSTRIDE + vcol(c0 + (p&3) + 1)] = vnew[p];
        __syncthreads();
    }
    // final v lives in vA (k=49 wrote vA)

    const int prow = pos_x[b];
    const int pcol = pos_y[b];
    if ((prow >> 1) == rp && (pcol >> 2) == cg) {
        const int p = ((prow & 1) << 2) | (pcol & 3);
        float win[9];
        #pragma unroll
        for (int s = 0; s < 3; s++)
            #pragma unroll
            for (int u = 0; u < 3; u++)
                win[s*3+u] = vA[(prow+s)*VSTRIDE + vcol(pcol + u)];
        float qv[10];
        #pragma unroll
        for (int ap = 0; ap < 5; ap++) {
            float lo, hi; upk2(myqr[ap*8 + p], lo, hi);
            qv[2*ap] = lo; qv[2*ap+1] = hi;
        }
        #pragma unroll
        for (int a = 0; a < 10; a++) {
            float t = qv[a];
            #pragma unroll
            for (int s = 0; s < 3; s++)
                #pragma unroll
                for (int u = 0; u < 3; u++)
                    t += wst[100 + a*9 + s*3 + u] * win[s*3+u];
            qv[a] = t;
        }
        #pragma unroll
        for (int j = 0; j < 8; j++) {
            float o = 0.f;
            #pragma unroll
            for (int a = 0; a < 10; a++) o += qv[a] * wst[190 + j*10 + a];
            out[b*8 + j] = o;
        }
    }
}

// ---------------- launch: setup -> stage constants -> main ------------------------
extern "C" void kernel_launch(void* const* d_in, const int* in_sizes, int n_in,
                              void* d_out, int out_size)
{
    const float* x     = (const float*)d_in[0];
    const int*   pos_x = (const int*)  d_in[1];
    const int*   pos_y = (const int*)  d_in[2];
    const float* h_w   = (const float*)d_in[3];
    const float* h_b   = (const float*)d_in[4];
    const float* r_w   = (const float*)d_in[5];
    const float* r_b   = (const float*)d_in[6];
    const float* q_w   = (const float*)d_in[7];
    const float* q_b   = (const float*)d_in[8];
    const float* fc_w  = (const float*)d_in[9];

    (void)in_sizes; (void)n_in; (void)out_size;

    cudaFuncSetAttribute(vin_main, cudaFuncAttributeMaxDynamicSharedMemorySize,
                         SMEM_BYTES);

    vin_setup<<<1, 288>>>(h_w, h_b, r_w, q_w);

    void* wq2_src = nullptr;
    cudaGetSymbolAddress(&wq2_src, g_wq2);
    cudaMemcpyToSymbolAsync(c_wq2, wq2_src, 90*sizeof(float), 0,
                            cudaMemcpyDeviceToDevice, 0);

    vin_main<<<128, BDIM, SMEM_BYTES>>>(x, pos_x, pos_y, r_b, q_w, q_b, fc_w,
                                        (float*)d_out);
}